// round 8
// baseline (speedup 1.0000x reference)
#include <cuda_runtime.h>
#include <cuda_fp16.h>
#include <math.h>
#include <stdint.h>

// ---------------- Problem constants ----------------
#define BATCH 4
#define LSEQ  1024
#define DMODEL 1024
#define HEADS 16
#define DKV   64
#define DFF   4096
#define TOK   (BATCH * LSEQ)
#define NBUCK 32
#define NEGINF (-1e9f)

// ---------------- Scratch ----------------
__device__ __half g_xnorm[TOK * DMODEL];
__device__ __half g_qkv[TOK * 3072];
__device__ __half g_kvx[TOK * 2048];
__device__ __half g_att[TOK * DMODEL];
__device__ float  g_h[TOK * DMODEL];
__device__ __half g_encr[TOK * DMODEL];
__device__ __half g_ffn[TOK * DFF];
__device__ __half g_wh[16 * 1024 * 1024];   // fp16 weights, transposed [N][K]
__device__ int    g_bucket[LSEQ];

#define WH_QKV 0                        // [3072][1024]
#define WH_CAQ (3 * 1048576)            // [1024][1024]
#define WH_KVX (4 * 1048576)            // [2048][1024]
#define WH_SAO (6 * 1048576)
#define WH_CAO (7 * 1048576)
#define WH_WI  (8 * 1048576)            // [4096][1024]
#define WH_WO  (12 * 1048576)           // [1024][4096]

// ---------------- helpers ----------------
__device__ __forceinline__ void mma_f16(float (&d)[4], const uint32_t (&a)[4],
                                        uint32_t b0, uint32_t b1) {
    asm volatile(
        "mma.sync.aligned.m16n8k16.row.col.f32.f16.f16.f32 "
        "{%0,%1,%2,%3}, {%4,%5,%6,%7}, {%8,%9}, {%0,%1,%2,%3};"
        : "+f"(d[0]), "+f"(d[1]), "+f"(d[2]), "+f"(d[3])
        : "r"(a[0]), "r"(a[1]), "r"(a[2]), "r"(a[3]), "r"(b0), "r"(b1));
}
__device__ __forceinline__ void ldsm4(uint32_t (&r)[4], uint32_t addr) {
    asm volatile("ldmatrix.sync.aligned.m8n8.x4.shared.b16 {%0,%1,%2,%3}, [%4];"
                 : "=r"(r[0]), "=r"(r[1]), "=r"(r[2]), "=r"(r[3]) : "r"(addr));
}
__device__ __forceinline__ void ldsm4t(uint32_t (&r)[4], uint32_t addr) {
    asm volatile("ldmatrix.sync.aligned.m8n8.x4.trans.shared.b16 {%0,%1,%2,%3}, [%4];"
                 : "=r"(r[0]), "=r"(r[1]), "=r"(r[2]), "=r"(r[3]) : "r"(addr));
}
__device__ __forceinline__ void cp16s(uint32_t dst, const void* src) {
    asm volatile("cp.async.cg.shared.global [%0], [%1], 16;" :: "r"(dst), "l"(src));
}
__device__ __forceinline__ void cp_commit() { asm volatile("cp.async.commit_group;"); }
__device__ __forceinline__ void cp_wait0()  { asm volatile("cp.async.wait_group 0;" ::: "memory"); }

// ---------------- prep ----------------
__global__ void transpose_h(const float* __restrict__ W, __half* __restrict__ Wt,
                            int K, int N) {
    __shared__ float t[32][33];
    int n0 = blockIdx.x * 32, k0 = blockIdx.y * 32;
    int x = threadIdx.x, y = threadIdx.y;
    #pragma unroll
    for (int i = 0; i < 32; i += 8)
        t[y + i][x] = W[(size_t)(k0 + y + i) * N + n0 + x];
    __syncthreads();
    #pragma unroll
    for (int i = 0; i < 32; i += 8)
        Wt[(size_t)(n0 + y + i) * K + k0 + x] = __float2half(t[x][y + i]);
}

__global__ void conv_half(const float* __restrict__ src, __half* __restrict__ dst, int n4) {
    int i = blockIdx.x * 256 + threadIdx.x;
    if (i < n4) {
        float4 v = ((const float4*)src)[i];
        __half2* d = (__half2*)(dst + (size_t)i * 4);
        d[0] = __floats2half2_rn(v.x, v.y);
        d[1] = __floats2half2_rn(v.z, v.w);
    }
}

// ---------------- RMS norm ----------------
template<bool HOUT>
__global__ void rms_kernel(const float* __restrict__ x,
                           const float* __restrict__ w, void* __restrict__ yv) {
    int row = blockIdx.x;
    const float* xr = x + (size_t)row * DMODEL;
    float s = 0.f;
    for (int i = threadIdx.x; i < DMODEL; i += 256) {
        float v = xr[i];
        s += v * v;
    }
    __shared__ float red[8];
    #pragma unroll
    for (int o = 16; o; o >>= 1) s += __shfl_xor_sync(0xffffffffu, s, o);
    if ((threadIdx.x & 31) == 0) red[threadIdx.x >> 5] = s;
    __syncthreads();
    if (threadIdx.x < 8) {
        float t = red[threadIdx.x];
        #pragma unroll
        for (int o = 4; o; o >>= 1) t += __shfl_xor_sync(0xffu, t, o);
        if (threadIdx.x == 0) red[0] = rsqrtf(t * (1.0f / DMODEL) + 1e-6f);
    }
    __syncthreads();
    float inv = red[0];
    for (int i = threadIdx.x; i < DMODEL; i += 256) {
        float v = xr[i] * inv * w[i];
        if (HOUT) ((__half*)yv)[(size_t)row * DMODEL + i] = __float2half(v);
        else      ((float*)yv)[(size_t)row * DMODEL + i] = v;
    }
}

// ---------------- fp16 GEMM: C[M,N] = A[M,K] @ Bt[N,K]^T (+R)(ReLU) -------
// Block 128x128x64, 128 thr = 4 warps (2M x 2N), warp tile 64x64.
// ldmatrix frags, fragment double-buffer across ks steps, cp.async 2-stage.
// smem rows: 128B data + 16B skew = 144B stride.
#define GSM_TILE 18432
#define GEMM_SMEM (4 * GSM_TILE)

template<bool RELU, bool RES, bool HOUT>
__global__ void __launch_bounds__(128, 2)
hgemm(const __half* __restrict__ A, const __half* __restrict__ B,
      const float* __restrict__ R, void* __restrict__ Cv,
      int M, int N, int K) {
    extern __shared__ char smc[];
    uint32_t S = (uint32_t)__cvta_generic_to_shared(smc);
    const int tid = threadIdx.x;
    const int warp = tid >> 5, lane = tid & 31;
    const int gid = lane >> 2, tg = lane & 3;
    const int wm = warp & 1, wn = warp >> 1;
    const int m0 = blockIdx.y * 128, n0 = blockIdx.x * 128;
    const __half* Ag = A + (size_t)m0 * K;
    const __half* Bg = B + (size_t)n0 * K;

    float acc[4][8][4];
    #pragma unroll
    for (int i = 0; i < 4; i++)
        #pragma unroll
        for (int j = 0; j < 8; j++)
            #pragma unroll
            for (int l = 0; l < 4; l++) acc[i][j][l] = 0.f;

    // A/B tile: 128 rows x 8 16B-chunks = 1024 chunks each; 128 threads x 8.
    #define GLOAD(kt, s) do {                                                 \
        uint32_t ab = S + (s) * GSM_TILE;                                     \
        uint32_t bb = S + 2 * GSM_TILE + (s) * GSM_TILE;                      \
        _Pragma("unroll")                                                     \
        for (int i = 0; i < 8; i++) {                                         \
            int idx = tid + i * 128;                                          \
            int r = idx >> 3, c = idx & 7;                                    \
            cp16s(ab + r * 144 + c * 16, Ag + (size_t)r * K + (kt) + c * 8);  \
            cp16s(bb + r * 144 + c * 16, Bg + (size_t)r * K + (kt) + c * 8);  \
        }                                                                     \
        cp_commit();                                                          \
    } while (0)

    // fragments for one 16-K step
    #define GFRAG(ab, bb, ks, af, bf) do {                                    \
        _Pragma("unroll")                                                     \
        for (int mt = 0; mt < 4; mt++)                                        \
            ldsm4((af)[mt], (ab) + (wm * 64 + mt * 16 + (lane & 15)) * 144    \
                          + (ks) * 32 + (lane >> 4) * 16);                    \
        _Pragma("unroll")                                                     \
        for (int g = 0; g < 4; g++)                                           \
            ldsm4((bf)[g], (bb) + (wn * 64 + g * 16 + ((lane >> 4) << 3) + (lane & 7)) * 144 \
                         + (ks) * 32 + ((lane >> 3) & 1) * 16);               \
    } while (0)

    GLOAD(0, 0);
    cp_wait0();
    __syncthreads();

    int s = 0;
    for (int kt = 0; kt < K; kt += 64) {
        bool more = (kt + 64 < K);
        if (more) GLOAD(kt + 64, s ^ 1);
        uint32_t ab = S + s * GSM_TILE;
        uint32_t bb = S + 2 * GSM_TILE + s * GSM_TILE;
        uint32_t af[2][4][4], bf[2][4][4];
        GFRAG(ab, bb, 0, af[0], bf[0]);
        #pragma unroll
        for (int ks = 0; ks < 4; ks++) {
            int cur = ks & 1;
            if (ks < 3) GFRAG(ab, bb, ks + 1, af[cur ^ 1], bf[cur ^ 1]);
            #pragma unroll
            for (int mt = 0; mt < 4; mt++)
                #pragma unroll
                for (int nt = 0; nt < 8; nt++)
                    mma_f16(acc[mt][nt], af[cur][mt],
                            bf[cur][nt >> 1][(nt & 1) * 2], bf[cur][nt >> 1][(nt & 1) * 2 + 1]);
        }
        if (more) cp_wait0();
        __syncthreads();
        s ^= 1;
    }

    #pragma unroll
    for (int mt = 0; mt < 4; mt++) {
        #pragma unroll
        for (int nt = 0; nt < 8; nt++) {
            int r0 = m0 + wm * 64 + mt * 16 + gid;
            int c  = n0 + wn * 64 + nt * 8 + tg * 2;
            float2 v0 = make_float2(acc[mt][nt][0], acc[mt][nt][1]);
            float2 v1 = make_float2(acc[mt][nt][2], acc[mt][nt][3]);
            if (RES) {
                float2 a0 = *(const float2*)(R + (size_t)r0 * N + c);
                float2 a1 = *(const float2*)(R + (size_t)(r0 + 8) * N + c);
                v0.x += a0.x; v0.y += a0.y; v1.x += a1.x; v1.y += a1.y;
            }
            if (RELU) {
                v0.x = fmaxf(v0.x, 0.f); v0.y = fmaxf(v0.y, 0.f);
                v1.x = fmaxf(v1.x, 0.f); v1.y = fmaxf(v1.y, 0.f);
            }
            if (HOUT) {
                __half* C = (__half*)Cv;
                *(__half2*)(C + (size_t)r0 * N + c)       = __floats2half2_rn(v0.x, v0.y);
                *(__half2*)(C + (size_t)(r0 + 8) * N + c) = __floats2half2_rn(v1.x, v1.y);
            } else {
                float* C = (float*)Cv;
                *(float2*)(C + (size_t)r0 * N + c) = v0;
                *(float2*)(C + (size_t)(r0 + 8) * N + c) = v1;
            }
        }
    }
    #undef GLOAD
    #undef GFRAG
}

// ---------------- T5 relative bucket table ----------------
__global__ void bucket_kernel() {
    int n = threadIdx.x;
    int b;
    if (n < 16) {
        b = n;
    } else {
        float nf = (float)n;
        int vl = 16 + (int)(logf(nf / 16.0f) / logf(8.0f) * 16.0f);
        b = vl < (NBUCK - 1) ? vl : (NBUCK - 1);
    }
    g_bucket[n] = b;
}

// ---------------- Fused fp16 flash attention (unchanged from R7) ----------
#define FQ_OFF 0
#define FK_OFF 18432
#define FV_OFF 36864
#define FP_OFF 55296
#define FMP_OFF 90112
#define FLP_OFF 92160
#define FMR_OFF 94208
#define FLR_OFF 95232
#define FL_SMEM 95744

template<bool SELF>
__global__ void __launch_bounds__(256)
flash_h(const __half* __restrict__ Qp, int qstride,
        const __half* __restrict__ Kp, int kstride,
        const __half* __restrict__ Vp, int vstride,
        const float* __restrict__ relb, const int* __restrict__ mask,
        __half* __restrict__ O) {
    extern __shared__ char smc[];
    uint32_t S = (uint32_t)__cvta_generic_to_shared(smc);
    float* mpart = (float*)(smc + FMP_OFF);
    float* lpart = (float*)(smc + FLP_OFF);
    float* mrun  = (float*)(smc + FMR_OFF);
    float* lrun  = (float*)(smc + FLR_OFF);

    int tid = threadIdx.x;
    int warp = tid >> 5, lane = tid & 31;
    int gid = lane >> 2, tg = lane & 3;
    int wm = warp & 1, wn = warp >> 1;
    int pm = warp & 3, pn = warp >> 2;
    int qt = blockIdx.x;
    int q0 = qt * 128;
    int bh = blockIdx.y;
    int b = bh >> 4, h = bh & 15;

    const __half* Qg = Qp + (size_t)(b * LSEQ + q0) * qstride + h * DKV;
    const __half* Kg = Kp + (size_t)(b * LSEQ) * kstride + h * DKV;
    const __half* Vg = Vp + (size_t)(b * LSEQ) * vstride + h * DKV;

    if (tid < 128) { mrun[tid] = -1e30f; lrun[tid] = 0.f; }

    #pragma unroll
    for (int i = 0; i < 4; i++) {
        int idx = tid + i * 256;
        int r = idx >> 3, c = idx & 7;
        cp16s(S + FQ_OFF + r * 144 + c * 16, Qg + (size_t)r * qstride + c * 8);
    }
    cp_commit();

    float oacc[2][4][4];
    #pragma unroll
    for (int i = 0; i < 2; i++)
        #pragma unroll
        for (int j = 0; j < 4; j++)
            #pragma unroll
            for (int l = 0; l < 4; l++) oacc[i][j][l] = 0.f;

    const int niter = SELF ? (qt + 1) : (LSEQ / 128);
    int p = 0;

    for (int it = 0; it < niter; it++) {
        int k0 = it * 128;
        #pragma unroll
        for (int i = 0; i < 4; i++) {
            int idx = tid + i * 256;
            int r = idx >> 3, c = idx & 7;
            cp16s(S + FK_OFF + r * 144 + c * 16, Kg + (size_t)(k0 + r) * kstride + c * 8);
            cp16s(S + FV_OFF + r * 144 + c * 16, Vg + (size_t)(k0 + r) * vstride + c * 8);
        }
        cp_commit();
        cp_wait0();
        __syncthreads();

        // ---- QK^T ----
        float sacc[4][4][4];
        #pragma unroll
        for (int i = 0; i < 4; i++)
            #pragma unroll
            for (int j = 0; j < 4; j++)
                #pragma unroll
                for (int l = 0; l < 4; l++) sacc[i][j][l] = 0.f;

        #pragma unroll
        for (int ks = 0; ks < 4; ks++) {
            uint32_t af[4][4], bf[2][4];
            #pragma unroll
            for (int mt = 0; mt < 4; mt++)
                ldsm4(af[mt], S + FQ_OFF + (wm * 64 + mt * 16 + (lane & 15)) * 144
                              + ks * 32 + (lane >> 4) * 16);
            #pragma unroll
            for (int g = 0; g < 2; g++)
                ldsm4(bf[g], S + FK_OFF + (wn * 32 + g * 16 + ((lane >> 4) << 3) + (lane & 7)) * 144
                             + ks * 32 + ((lane >> 3) & 1) * 16);
            #pragma unroll
            for (int mt = 0; mt < 4; mt++)
                #pragma unroll
                for (int nt = 0; nt < 4; nt++)
                    mma_f16(sacc[mt][nt], af[mt],
                            bf[nt >> 1][(nt & 1) * 2], bf[nt >> 1][(nt & 1) * 2 + 1]);
        }

        // ---- bias + mask ----
        bool cok[4][2];
        int ccol[4];
        #pragma unroll
        for (int nf = 0; nf < 4; nf++) {
            int c = k0 + wn * 32 + nf * 8 + tg * 2;
            ccol[nf] = c;
            cok[nf][0] = mask[b * LSEQ + c] > 0;
            cok[nf][1] = mask[b * LSEQ + c + 1] > 0;
        }
        #pragma unroll
        for (int mf = 0; mf < 4; mf++) {
            #pragma unroll
            for (int half = 0; half < 2; half++) {
                int qi = q0 + wm * 64 + mf * 16 + gid + half * 8;
                #pragma unroll
                for (int nf = 0; nf < 4; nf++) {
                    int c = ccol[nf];
                    if (SELF) {
                        int d0 = qi - c, d1 = d0 - 1;
                        sacc[mf][nf][half * 2]     += relb[g_bucket[d0 > 0 ? d0 : 0] * HEADS + h];
                        sacc[mf][nf][half * 2 + 1] += relb[g_bucket[d1 > 0 ? d1 : 0] * HEADS + h];
                        if (!((c     <= qi) && cok[nf][0])) sacc[mf][nf][half * 2]     += NEGINF;
                        if (!((c + 1 <= qi) && cok[nf][1])) sacc[mf][nf][half * 2 + 1] += NEGINF;
                    } else {
                        if (!cok[nf][0]) sacc[mf][nf][half * 2]     += NEGINF;
                        if (!cok[nf][1]) sacc[mf][nf][half * 2 + 1] += NEGINF;
                    }
                }
            }
        }

        // ---- partial row max ----
        #pragma unroll
        for (int mf = 0; mf < 4; mf++) {
            float mx0 = -1e30f, mx1 = -1e30f;
            #pragma unroll
            for (int nf = 0; nf < 4; nf++) {
                mx0 = fmaxf(mx0, fmaxf(sacc[mf][nf][0], sacc[mf][nf][1]));
                mx1 = fmaxf(mx1, fmaxf(sacc[mf][nf][2], sacc[mf][nf][3]));
            }
            mx0 = fmaxf(mx0, __shfl_xor_sync(0xffffffffu, mx0, 1));
            mx0 = fmaxf(mx0, __shfl_xor_sync(0xffffffffu, mx0, 2));
            mx1 = fmaxf(mx1, __shfl_xor_sync(0xffffffffu, mx1, 1));
            mx1 = fmaxf(mx1, __shfl_xor_sync(0xffffffffu, mx1, 2));
            if (tg == 0) {
                int r0 = wm * 64 + mf * 16 + gid;
                mpart[r0 * 4 + wn] = mx0;
                mpart[(r0 + 8) * 4 + wn] = mx1;
            }
        }
        __syncthreads();

        // ---- m_new, exp, P store (half), partial sums ----
        float* mold  = mrun + p * 128;
        float* mnewa = mrun + (p ^ 1) * 128;
        #pragma unroll
        for (int mf = 0; mf < 4; mf++) {
            #pragma unroll
            for (int half = 0; half < 2; half++) {
                int r = wm * 64 + mf * 16 + gid + half * 8;
                float mt = fmaxf(fmaxf(mpart[r * 4 + 0], mpart[r * 4 + 1]),
                                 fmaxf(mpart[r * 4 + 2], mpart[r * 4 + 3]));
                float mn = fmaxf(mold[r], mt);
                if (wn == 0 && tg == 0) mnewa[r] = mn;
                float sum = 0.f;
                #pragma unroll
                for (int nf = 0; nf < 4; nf++) {
                    float e0 = __expf(sacc[mf][nf][half * 2]     - mn);
                    float e1 = __expf(sacc[mf][nf][half * 2 + 1] - mn);
                    sum += e0 + e1;
                    int col = wn * 32 + nf * 8 + tg * 2;
                    *(__half2*)(smc + FP_OFF + r * 272 + col * 2) = __floats2half2_rn(e0, e1);
                }
                sum += __shfl_xor_sync(0xffffffffu, sum, 1);
                sum += __shfl_xor_sync(0xffffffffu, sum, 2);
                if (tg == 0) lpart[r * 4 + wn] = sum;
            }
        }
        __syncthreads();

        // ---- rescale O, update running sum ----
        #pragma unroll
        for (int mt2 = 0; mt2 < 2; mt2++) {
            #pragma unroll
            for (int half = 0; half < 2; half++) {
                int r = pm * 32 + mt2 * 16 + gid + half * 8;
                float rs = __expf(mold[r] - mnewa[r]);
                #pragma unroll
                for (int nf = 0; nf < 4; nf++) {
                    oacc[mt2][nf][half * 2]     *= rs;
                    oacc[mt2][nf][half * 2 + 1] *= rs;
                }
                if (pn == 0 && tg == 0)
                    lrun[r] = lrun[r] * rs + lpart[r * 4 + 0] + lpart[r * 4 + 1]
                                           + lpart[r * 4 + 2] + lpart[r * 4 + 3];
            }
        }

        // ---- P @ V ----
        #pragma unroll
        for (int ks = 0; ks < 8; ks++) {
            uint32_t af[2][4], bf[2][4];
            #pragma unroll
            for (int mt2 = 0; mt2 < 2; mt2++)
                ldsm4(af[mt2], S + FP_OFF + (pm * 32 + mt2 * 16 + (lane & 15)) * 272
                               + ks * 32 + (lane >> 4) * 16);
            #pragma unroll
            for (int g = 0; g < 2; g++)
                ldsm4t(bf[g], S + FV_OFF + (ks * 16 + ((lane >> 3) & 1) * 8 + (lane & 7)) * 144
                              + pn * 64 + g * 32 + (lane >> 4) * 16);
            #pragma unroll
            for (int mt2 = 0; mt2 < 2; mt2++)
                #pragma unroll
                for (int nt = 0; nt < 4; nt++)
                    mma_f16(oacc[mt2][nt], af[mt2],
                            bf[nt >> 1][(nt & 1) * 2], bf[nt >> 1][(nt & 1) * 2 + 1]);
        }

        __syncthreads();
        p ^= 1;
    }

    // ---- normalize, store half ----
    #pragma unroll
    for (int mt2 = 0; mt2 < 2; mt2++) {
        int rloc0 = pm * 32 + mt2 * 16 + gid;
        float inv0 = 1.0f / lrun[rloc0];
        float inv1 = 1.0f / lrun[rloc0 + 8];
        #pragma unroll
        for (int nf = 0; nf < 4; nf++) {
            int col = h * DKV + pn * 32 + nf * 8 + tg * 2;
            size_t row0 = (size_t)(b * LSEQ + q0 + rloc0);
            *(__half2*)(O + row0 * DMODEL + col)
                = __floats2half2_rn(oacc[mt2][nf][0] * inv0, oacc[mt2][nf][1] * inv0);
            *(__half2*)(O + (row0 + 8) * DMODEL + col)
                = __floats2half2_rn(oacc[mt2][nf][2] * inv1, oacc[mt2][nf][3] * inv1);
        }
    }
}

// ---------------- Orchestration -------------------------------------------
extern "C" void kernel_launch(void* const* d_in, const int* in_sizes, int n_in,
                              void* d_out, int out_size) {
    const float* enc    = (const float*)d_in[0];
    const float* hid    = (const float*)d_in[1];
    const float* ln1_w  = (const float*)d_in[2];
    const float* sa_q   = (const float*)d_in[3];
    const float* sa_k   = (const float*)d_in[4];
    const float* sa_v   = (const float*)d_in[5];
    const float* sa_o   = (const float*)d_in[6];
    const float* relb   = (const float*)d_in[7];
    const float* ln2_w  = (const float*)d_in[8];
    const float* ca_q   = (const float*)d_in[9];
    const float* ca_k   = (const float*)d_in[10];
    const float* ca_v   = (const float*)d_in[11];
    const float* ca_o   = (const float*)d_in[12];
    const float* ln3_w  = (const float*)d_in[13];
    const float* wi     = (const float*)d_in[14];
    const float* wo     = (const float*)d_in[15];
    const float* flnw   = (const float*)d_in[16];
    const int*   emask  = (const int*)d_in[17];
    const int*   dmask  = (const int*)d_in[18];
    float* out = (float*)d_out;

    __half *xn, *qkv, *kvx, *att, *encr, *ffn, *wh;
    float *h;
    cudaGetSymbolAddress((void**)&xn,   g_xnorm);
    cudaGetSymbolAddress((void**)&qkv,  g_qkv);
    cudaGetSymbolAddress((void**)&kvx,  g_kvx);
    cudaGetSymbolAddress((void**)&att,  g_att);
    cudaGetSymbolAddress((void**)&h,    g_h);
    cudaGetSymbolAddress((void**)&encr, g_encr);
    cudaGetSymbolAddress((void**)&ffn,  g_ffn);
    cudaGetSymbolAddress((void**)&wh,   g_wh);

    cudaFuncSetAttribute(hgemm<false,false,true>, cudaFuncAttributeMaxDynamicSharedMemorySize, GEMM_SMEM);
    cudaFuncSetAttribute(hgemm<false,true,false>, cudaFuncAttributeMaxDynamicSharedMemorySize, GEMM_SMEM);
    cudaFuncSetAttribute(hgemm<true,false,true>,  cudaFuncAttributeMaxDynamicSharedMemorySize, GEMM_SMEM);
    cudaFuncSetAttribute(flash_h<true>,  cudaFuncAttributeMaxDynamicSharedMemorySize, FL_SMEM);
    cudaFuncSetAttribute(flash_h<false>, cudaFuncAttributeMaxDynamicSharedMemorySize, FL_SMEM);

    dim3 tb(32, 8);
    dim3 tDD(32, 32);
    dim3 gDD(8, 32);
    dim3 gQKV(24, 32);
    dim3 gKV(16, 32);
    dim3 gDF(32, 32);
    dim3 gFlash(LSEQ / 128, BATCH * HEADS);

    // ---- launches 1-5: QKV weight prep, bucket, rms ----
    transpose_h<<<tDD, tb>>>(sa_q, wh + WH_QKV,               DMODEL, DMODEL);   // 1
    transpose_h<<<tDD, tb>>>(sa_k, wh + WH_QKV + 1048576,     DMODEL, DMODEL);   // 2
    transpose_h<<<tDD, tb>>>(sa_v, wh + WH_QKV + 2 * 1048576, DMODEL, DMODEL);   // 3
    bucket_kernel<<<1, 1024>>>();                                                 // 4
    rms_kernel<true><<<TOK, 256>>>(hid, ln1_w, xn);                               // 5

    // ---- launch 6 (ncu -s 5 -c 1 lands HERE): the big fused QKV GEMM ----
    hgemm<false,false,true><<<gQKV, 128, GEMM_SMEM>>>(xn, wh + WH_QKV, nullptr, qkv, TOK, 3072, DMODEL);

    // ---- remaining weight prep (before their consumers) ----
    transpose_h<<<tDD, tb>>>(ca_q, wh + WH_CAQ,               DMODEL, DMODEL);
    transpose_h<<<tDD, tb>>>(ca_k, wh + WH_KVX,               DMODEL, DMODEL);
    transpose_h<<<tDD, tb>>>(ca_v, wh + WH_KVX + 1048576,     DMODEL, DMODEL);
    transpose_h<<<tDD, tb>>>(sa_o, wh + WH_SAO,               DMODEL, DMODEL);
    transpose_h<<<tDD, tb>>>(ca_o, wh + WH_CAO,               DMODEL, DMODEL);
    transpose_h<<<dim3(128, 32), tb>>>(wi, wh + WH_WI, DMODEL, DFF);
    transpose_h<<<dim3(32, 128), tb>>>(wo, wh + WH_WO, DFF, DMODEL);
    conv_half<<<(TOK * DMODEL / 4 + 255) / 256, 256>>>(enc, encr, TOK * DMODEL / 4);

    // ---- Self-attention ----
    flash_h<true><<<gFlash, 256, FL_SMEM>>>(qkv, 3072, qkv + 1024, 3072, qkv + 2048, 3072,
                                            relb, dmask, att);
    hgemm<false,true,false><<<gDD, 128, GEMM_SMEM>>>(att, wh + WH_SAO, hid, h, TOK, DMODEL, DMODEL);

    // ---- Cross-attention ----
    rms_kernel<true><<<TOK, 256>>>(h, ln2_w, xn);
    hgemm<false,false,true><<<gDD, 128, GEMM_SMEM>>>(xn, wh + WH_CAQ, nullptr, qkv, TOK, DMODEL, DMODEL);
    hgemm<false,false,true><<<gKV, 128, GEMM_SMEM>>>(encr, wh + WH_KVX, nullptr, kvx, TOK, 2048, DMODEL);
    flash_h<false><<<gFlash, 256, FL_SMEM>>>(qkv, 1024, kvx, 2048, kvx + 1024, 2048,
                                             nullptr, emask, att);
    hgemm<false,true,false><<<gDD, 128, GEMM_SMEM>>>(att, wh + WH_CAO, h, h, TOK, DMODEL, DMODEL);

    // ---- FFN ----
    rms_kernel<true><<<TOK, 256>>>(h, ln3_w, xn);
    hgemm<true,false,true><<<gDF, 128, GEMM_SMEM>>>(xn, wh + WH_WI, nullptr, ffn, TOK, DFF, DMODEL);
    hgemm<false,true,false><<<gDD, 128, GEMM_SMEM>>>(ffn, wh + WH_WO, h, h, TOK, DMODEL, DFF);

    // ---- Final norm ----
    rms_kernel<false><<<TOK, 256>>>(h, flnw, out);
}

// round 9
// speedup vs baseline: 1.0535x; 1.0535x over previous
#include <cuda_runtime.h>
#include <cuda_fp16.h>
#include <math.h>
#include <stdint.h>

// ---------------- Problem constants ----------------
#define BATCH 4
#define LSEQ  1024
#define DMODEL 1024
#define HEADS 16
#define DKV   64
#define DFF   4096
#define TOK   (BATCH * LSEQ)
#define NBUCK 32
#define NEGINF (-1e9f)

// ---------------- Scratch ----------------
__device__ __half g_xnorm[TOK * DMODEL];
__device__ __half g_qkv[TOK * 3072];
__device__ __half g_kvx[TOK * 2048];
__device__ __half g_att[TOK * DMODEL];
__device__ float  g_h[TOK * DMODEL];
__device__ __half g_encr[TOK * DMODEL];
__device__ __half g_ffn[TOK * DFF];
__device__ __half g_wh[16 * 1024 * 1024];   // fp16 weights, transposed [N][K]
__device__ int    g_bucket[LSEQ];

#define WH_QKV 0                        // [3072][1024]
#define WH_CAQ (3 * 1048576)            // [1024][1024]
#define WH_KVX (4 * 1048576)            // [2048][1024]
#define WH_SAO (6 * 1048576)
#define WH_CAO (7 * 1048576)
#define WH_WI  (8 * 1048576)            // [4096][1024]
#define WH_WO  (12 * 1048576)           // [1024][4096]

// ---------------- helpers ----------------
__device__ __forceinline__ void mma_f16(float (&d)[4], const uint32_t (&a)[4],
                                        uint32_t b0, uint32_t b1) {
    asm volatile(
        "mma.sync.aligned.m16n8k16.row.col.f32.f16.f16.f32 "
        "{%0,%1,%2,%3}, {%4,%5,%6,%7}, {%8,%9}, {%0,%1,%2,%3};"
        : "+f"(d[0]), "+f"(d[1]), "+f"(d[2]), "+f"(d[3])
        : "r"(a[0]), "r"(a[1]), "r"(a[2]), "r"(a[3]), "r"(b0), "r"(b1));
}
__device__ __forceinline__ void ldsm4(uint32_t (&r)[4], uint32_t addr) {
    asm volatile("ldmatrix.sync.aligned.m8n8.x4.shared.b16 {%0,%1,%2,%3}, [%4];"
                 : "=r"(r[0]), "=r"(r[1]), "=r"(r[2]), "=r"(r[3]) : "r"(addr));
}
__device__ __forceinline__ void ldsm4t(uint32_t (&r)[4], uint32_t addr) {
    asm volatile("ldmatrix.sync.aligned.m8n8.x4.trans.shared.b16 {%0,%1,%2,%3}, [%4];"
                 : "=r"(r[0]), "=r"(r[1]), "=r"(r[2]), "=r"(r[3]) : "r"(addr));
}
__device__ __forceinline__ void cp16s(uint32_t dst, const void* src) {
    asm volatile("cp.async.cg.shared.global [%0], [%1], 16;" :: "r"(dst), "l"(src));
}
__device__ __forceinline__ void cp_commit() { asm volatile("cp.async.commit_group;"); }
__device__ __forceinline__ void cp_wait0()  { asm volatile("cp.async.wait_group 0;" ::: "memory"); }

// ---------------- prep: fast 64x64 transpose fp32[K][N] -> fp16[N][K] -----
__global__ void __launch_bounds__(256)
transpose_h2(const float* __restrict__ W, __half* __restrict__ Wt,
             int K, int N) {
    __shared__ float t[64][65];
    int n0 = blockIdx.x * 64, k0 = blockIdx.y * 64;
    int tid = threadIdx.x;
    int row = tid >> 2;              // 0..63
    int qc  = tid & 3;               // 0..3
    #pragma unroll
    for (int j = 0; j < 4; j++) {
        float4 v = *(const float4*)(W + (size_t)(k0 + row) * N + n0 + qc * 16 + j * 4);
        t[row][qc * 16 + j * 4 + 0] = v.x;
        t[row][qc * 16 + j * 4 + 1] = v.y;
        t[row][qc * 16 + j * 4 + 2] = v.z;
        t[row][qc * 16 + j * 4 + 3] = v.w;
    }
    __syncthreads();
    // write Wt[n0+row][k0 + qc*16 .. +15] as 2 x 8-half vectors
    #pragma unroll
    for (int j = 0; j < 2; j++) {
        __half hbuf[8];
        #pragma unroll
        for (int e = 0; e < 8; e++)
            hbuf[e] = __float2half(t[qc * 16 + j * 8 + e][row]);
        *(uint4*)(Wt + (size_t)(n0 + row) * K + k0 + qc * 16 + j * 8) = *(uint4*)hbuf;
    }
}

__global__ void conv_half(const float* __restrict__ src, __half* __restrict__ dst, int n4) {
    int i = blockIdx.x * 256 + threadIdx.x;
    if (i < n4) {
        float4 v = ((const float4*)src)[i];
        __half2* d = (__half2*)(dst + (size_t)i * 4);
        d[0] = __floats2half2_rn(v.x, v.y);
        d[1] = __floats2half2_rn(v.z, v.w);
    }
}

// ---------------- RMS norm (vectorized: 256 thr x float4 = 1024) ----------
template<bool HOUT>
__global__ void rms_kernel(const float* __restrict__ x,
                           const float* __restrict__ w, void* __restrict__ yv) {
    int row = blockIdx.x;
    int tid = threadIdx.x;
    float4 v = ((const float4*)(x + (size_t)row * DMODEL))[tid];
    float s = v.x * v.x + v.y * v.y + v.z * v.z + v.w * v.w;
    __shared__ float red[8];
    #pragma unroll
    for (int o = 16; o; o >>= 1) s += __shfl_xor_sync(0xffffffffu, s, o);
    if ((tid & 31) == 0) red[tid >> 5] = s;
    __syncthreads();
    if (tid < 8) {
        float t = red[tid];
        #pragma unroll
        for (int o = 4; o; o >>= 1) t += __shfl_xor_sync(0xffu, t, o);
        if (tid == 0) red[0] = rsqrtf(t * (1.0f / DMODEL) + 1e-6f);
    }
    __syncthreads();
    float inv = red[0];
    float4 wv = ((const float4*)w)[tid];
    float a = v.x * inv * wv.x, b = v.y * inv * wv.y;
    float c = v.z * inv * wv.z, d = v.w * inv * wv.w;
    if (HOUT) {
        __half2* yr = (__half2*)yv + (size_t)row * (DMODEL / 2);
        yr[tid * 2]     = __floats2half2_rn(a, b);
        yr[tid * 2 + 1] = __floats2half2_rn(c, d);
    } else {
        ((float4*)yv)[(size_t)row * (DMODEL / 4) + tid] = make_float4(a, b, c, d);
    }
}

// ---------------- fp16 GEMM (R7 config: 256 thr, 8 warps 2Mx4N, 64x32) ----
#define GSM_TILE 18432
#define GEMM_SMEM (4 * GSM_TILE)

template<bool RELU, bool RES, bool HOUT>
__global__ void __launch_bounds__(256, 2)
hgemm(const __half* __restrict__ A, const __half* __restrict__ B,
      const float* __restrict__ R, void* __restrict__ Cv,
      int M, int N, int K) {
    extern __shared__ char smc[];
    uint32_t S = (uint32_t)__cvta_generic_to_shared(smc);
    const int tid = threadIdx.x;
    const int warp = tid >> 5, lane = tid & 31;
    const int gid = lane >> 2, tg = lane & 3;
    const int wm = warp & 1, wn = warp >> 1;
    const int m0 = blockIdx.y * 128, n0 = blockIdx.x * 128;
    const __half* Ag = A + (size_t)m0 * K;
    const __half* Bg = B + (size_t)n0 * K;

    float acc[4][4][4];
    #pragma unroll
    for (int i = 0; i < 4; i++)
        #pragma unroll
        for (int j = 0; j < 4; j++)
            #pragma unroll
            for (int l = 0; l < 4; l++) acc[i][j][l] = 0.f;

    #define GLOAD(kt, s) do {                                                 \
        uint32_t ab = S + (s) * GSM_TILE;                                     \
        uint32_t bb = S + 2 * GSM_TILE + (s) * GSM_TILE;                      \
        _Pragma("unroll")                                                     \
        for (int i = 0; i < 4; i++) {                                         \
            int idx = tid + i * 256;                                          \
            int r = idx >> 3, c = idx & 7;                                    \
            cp16s(ab + r * 144 + c * 16, Ag + (size_t)r * K + (kt) + c * 8);  \
            cp16s(bb + r * 144 + c * 16, Bg + (size_t)r * K + (kt) + c * 8);  \
        }                                                                     \
        cp_commit();                                                          \
    } while (0)

    GLOAD(0, 0);
    cp_wait0();
    __syncthreads();

    int s = 0;
    for (int kt = 0; kt < K; kt += 64) {
        bool more = (kt + 64 < K);
        if (more) GLOAD(kt + 64, s ^ 1);
        uint32_t ab = S + s * GSM_TILE;
        uint32_t bb = S + 2 * GSM_TILE + s * GSM_TILE;
        #pragma unroll
        for (int ks = 0; ks < 4; ks++) {
            uint32_t af[4][4], bf[2][4];
            #pragma unroll
            for (int mt = 0; mt < 4; mt++)
                ldsm4(af[mt], ab + (wm * 64 + mt * 16 + (lane & 15)) * 144
                              + ks * 32 + (lane >> 4) * 16);
            #pragma unroll
            for (int g = 0; g < 2; g++)
                ldsm4(bf[g], bb + (wn * 32 + g * 16 + ((lane >> 4) << 3) + (lane & 7)) * 144
                             + ks * 32 + ((lane >> 3) & 1) * 16);
            #pragma unroll
            for (int mt = 0; mt < 4; mt++)
                #pragma unroll
                for (int nt = 0; nt < 4; nt++)
                    mma_f16(acc[mt][nt], af[mt],
                            bf[nt >> 1][(nt & 1) * 2], bf[nt >> 1][(nt & 1) * 2 + 1]);
        }
        if (more) cp_wait0();
        __syncthreads();
        s ^= 1;
    }

    #pragma unroll
    for (int mt = 0; mt < 4; mt++) {
        #pragma unroll
        for (int nt = 0; nt < 4; nt++) {
            int r0 = m0 + wm * 64 + mt * 16 + gid;
            int c  = n0 + wn * 32 + nt * 8 + tg * 2;
            float2 v0 = make_float2(acc[mt][nt][0], acc[mt][nt][1]);
            float2 v1 = make_float2(acc[mt][nt][2], acc[mt][nt][3]);
            if (RES) {
                float2 a0 = *(const float2*)(R + (size_t)r0 * N + c);
                float2 a1 = *(const float2*)(R + (size_t)(r0 + 8) * N + c);
                v0.x += a0.x; v0.y += a0.y; v1.x += a1.x; v1.y += a1.y;
            }
            if (RELU) {
                v0.x = fmaxf(v0.x, 0.f); v0.y = fmaxf(v0.y, 0.f);
                v1.x = fmaxf(v1.x, 0.f); v1.y = fmaxf(v1.y, 0.f);
            }
            if (HOUT) {
                __half* C = (__half*)Cv;
                *(__half2*)(C + (size_t)r0 * N + c)       = __floats2half2_rn(v0.x, v0.y);
                *(__half2*)(C + (size_t)(r0 + 8) * N + c) = __floats2half2_rn(v1.x, v1.y);
            } else {
                float* C = (float*)Cv;
                *(float2*)(C + (size_t)r0 * N + c) = v0;
                *(float2*)(C + (size_t)(r0 + 8) * N + c) = v1;
            }
        }
    }
    #undef GLOAD
}

// ---------------- T5 relative bucket table ----------------
__global__ void bucket_kernel() {
    int n = threadIdx.x;
    int b;
    if (n < 16) {
        b = n;
    } else {
        float nf = (float)n;
        int vl = 16 + (int)(logf(nf / 16.0f) / logf(8.0f) * 16.0f);
        b = vl < (NBUCK - 1) ? vl : (NBUCK - 1);
    }
    g_bucket[n] = b;
}

// ---------------- Fused fp16 flash attention (R7, unchanged) --------------
#define FQ_OFF 0
#define FK_OFF 18432
#define FV_OFF 36864
#define FP_OFF 55296
#define FMP_OFF 90112
#define FLP_OFF 92160
#define FMR_OFF 94208
#define FLR_OFF 95232
#define FL_SMEM 95744

template<bool SELF>
__global__ void __launch_bounds__(256)
flash_h(const __half* __restrict__ Qp, int qstride,
        const __half* __restrict__ Kp, int kstride,
        const __half* __restrict__ Vp, int vstride,
        const float* __restrict__ relb, const int* __restrict__ mask,
        __half* __restrict__ O) {
    extern __shared__ char smc[];
    uint32_t S = (uint32_t)__cvta_generic_to_shared(smc);
    float* mpart = (float*)(smc + FMP_OFF);
    float* lpart = (float*)(smc + FLP_OFF);
    float* mrun  = (float*)(smc + FMR_OFF);
    float* lrun  = (float*)(smc + FLR_OFF);

    int tid = threadIdx.x;
    int warp = tid >> 5, lane = tid & 31;
    int gid = lane >> 2, tg = lane & 3;
    int wm = warp & 1, wn = warp >> 1;
    int pm = warp & 3, pn = warp >> 2;
    int qt = blockIdx.x;
    int q0 = qt * 128;
    int bh = blockIdx.y;
    int b = bh >> 4, h = bh & 15;

    const __half* Qg = Qp + (size_t)(b * LSEQ + q0) * qstride + h * DKV;
    const __half* Kg = Kp + (size_t)(b * LSEQ) * kstride + h * DKV;
    const __half* Vg = Vp + (size_t)(b * LSEQ) * vstride + h * DKV;

    if (tid < 128) { mrun[tid] = -1e30f; lrun[tid] = 0.f; }

    #pragma unroll
    for (int i = 0; i < 4; i++) {
        int idx = tid + i * 256;
        int r = idx >> 3, c = idx & 7;
        cp16s(S + FQ_OFF + r * 144 + c * 16, Qg + (size_t)r * qstride + c * 8);
    }
    cp_commit();

    float oacc[2][4][4];
    #pragma unroll
    for (int i = 0; i < 2; i++)
        #pragma unroll
        for (int j = 0; j < 4; j++)
            #pragma unroll
            for (int l = 0; l < 4; l++) oacc[i][j][l] = 0.f;

    const int niter = SELF ? (qt + 1) : (LSEQ / 128);
    int p = 0;

    for (int it = 0; it < niter; it++) {
        int k0 = it * 128;
        #pragma unroll
        for (int i = 0; i < 4; i++) {
            int idx = tid + i * 256;
            int r = idx >> 3, c = idx & 7;
            cp16s(S + FK_OFF + r * 144 + c * 16, Kg + (size_t)(k0 + r) * kstride + c * 8);
            cp16s(S + FV_OFF + r * 144 + c * 16, Vg + (size_t)(k0 + r) * vstride + c * 8);
        }
        cp_commit();
        cp_wait0();
        __syncthreads();

        // ---- QK^T ----
        float sacc[4][4][4];
        #pragma unroll
        for (int i = 0; i < 4; i++)
            #pragma unroll
            for (int j = 0; j < 4; j++)
                #pragma unroll
                for (int l = 0; l < 4; l++) sacc[i][j][l] = 0.f;

        #pragma unroll
        for (int ks = 0; ks < 4; ks++) {
            uint32_t af[4][4], bf[2][4];
            #pragma unroll
            for (int mt = 0; mt < 4; mt++)
                ldsm4(af[mt], S + FQ_OFF + (wm * 64 + mt * 16 + (lane & 15)) * 144
                              + ks * 32 + (lane >> 4) * 16);
            #pragma unroll
            for (int g = 0; g < 2; g++)
                ldsm4(bf[g], S + FK_OFF + (wn * 32 + g * 16 + ((lane >> 4) << 3) + (lane & 7)) * 144
                             + ks * 32 + ((lane >> 3) & 1) * 16);
            #pragma unroll
            for (int mt = 0; mt < 4; mt++)
                #pragma unroll
                for (int nt = 0; nt < 4; nt++)
                    mma_f16(sacc[mt][nt], af[mt],
                            bf[nt >> 1][(nt & 1) * 2], bf[nt >> 1][(nt & 1) * 2 + 1]);
        }

        // ---- bias + mask ----
        bool cok[4][2];
        int ccol[4];
        #pragma unroll
        for (int nf = 0; nf < 4; nf++) {
            int c = k0 + wn * 32 + nf * 8 + tg * 2;
            ccol[nf] = c;
            cok[nf][0] = mask[b * LSEQ + c] > 0;
            cok[nf][1] = mask[b * LSEQ + c + 1] > 0;
        }
        #pragma unroll
        for (int mf = 0; mf < 4; mf++) {
            #pragma unroll
            for (int half = 0; half < 2; half++) {
                int qi = q0 + wm * 64 + mf * 16 + gid + half * 8;
                #pragma unroll
                for (int nf = 0; nf < 4; nf++) {
                    int c = ccol[nf];
                    if (SELF) {
                        int d0 = qi - c, d1 = d0 - 1;
                        sacc[mf][nf][half * 2]     += relb[g_bucket[d0 > 0 ? d0 : 0] * HEADS + h];
                        sacc[mf][nf][half * 2 + 1] += relb[g_bucket[d1 > 0 ? d1 : 0] * HEADS + h];
                        if (!((c     <= qi) && cok[nf][0])) sacc[mf][nf][half * 2]     += NEGINF;
                        if (!((c + 1 <= qi) && cok[nf][1])) sacc[mf][nf][half * 2 + 1] += NEGINF;
                    } else {
                        if (!cok[nf][0]) sacc[mf][nf][half * 2]     += NEGINF;
                        if (!cok[nf][1]) sacc[mf][nf][half * 2 + 1] += NEGINF;
                    }
                }
            }
        }

        // ---- partial row max ----
        #pragma unroll
        for (int mf = 0; mf < 4; mf++) {
            float mx0 = -1e30f, mx1 = -1e30f;
            #pragma unroll
            for (int nf = 0; nf < 4; nf++) {
                mx0 = fmaxf(mx0, fmaxf(sacc[mf][nf][0], sacc[mf][nf][1]));
                mx1 = fmaxf(mx1, fmaxf(sacc[mf][nf][2], sacc[mf][nf][3]));
            }
            mx0 = fmaxf(mx0, __shfl_xor_sync(0xffffffffu, mx0, 1));
            mx0 = fmaxf(mx0, __shfl_xor_sync(0xffffffffu, mx0, 2));
            mx1 = fmaxf(mx1, __shfl_xor_sync(0xffffffffu, mx1, 1));
            mx1 = fmaxf(mx1, __shfl_xor_sync(0xffffffffu, mx1, 2));
            if (tg == 0) {
                int r0 = wm * 64 + mf * 16 + gid;
                mpart[r0 * 4 + wn] = mx0;
                mpart[(r0 + 8) * 4 + wn] = mx1;
            }
        }
        __syncthreads();

        // ---- m_new, exp, P store (half), partial sums ----
        float* mold  = mrun + p * 128;
        float* mnewa = mrun + (p ^ 1) * 128;
        #pragma unroll
        for (int mf = 0; mf < 4; mf++) {
            #pragma unroll
            for (int half = 0; half < 2; half++) {
                int r = wm * 64 + mf * 16 + gid + half * 8;
                float mt = fmaxf(fmaxf(mpart[r * 4 + 0], mpart[r * 4 + 1]),
                                 fmaxf(mpart[r * 4 + 2], mpart[r * 4 + 3]));
                float mn = fmaxf(mold[r], mt);
                if (wn == 0 && tg == 0) mnewa[r] = mn;
                float sum = 0.f;
                #pragma unroll
                for (int nf = 0; nf < 4; nf++) {
                    float e0 = __expf(sacc[mf][nf][half * 2]     - mn);
                    float e1 = __expf(sacc[mf][nf][half * 2 + 1] - mn);
                    sum += e0 + e1;
                    int col = wn * 32 + nf * 8 + tg * 2;
                    *(__half2*)(smc + FP_OFF + r * 272 + col * 2) = __floats2half2_rn(e0, e1);
                }
                sum += __shfl_xor_sync(0xffffffffu, sum, 1);
                sum += __shfl_xor_sync(0xffffffffu, sum, 2);
                if (tg == 0) lpart[r * 4 + wn] = sum;
            }
        }
        __syncthreads();

        // ---- rescale O, update running sum ----
        #pragma unroll
        for (int mt2 = 0; mt2 < 2; mt2++) {
            #pragma unroll
            for (int half = 0; half < 2; half++) {
                int r = pm * 32 + mt2 * 16 + gid + half * 8;
                float rs = __expf(mold[r] - mnewa[r]);
                #pragma unroll
                for (int nf = 0; nf < 4; nf++) {
                    oacc[mt2][nf][half * 2]     *= rs;
                    oacc[mt2][nf][half * 2 + 1] *= rs;
                }
                if (pn == 0 && tg == 0)
                    lrun[r] = lrun[r] * rs + lpart[r * 4 + 0] + lpart[r * 4 + 1]
                                           + lpart[r * 4 + 2] + lpart[r * 4 + 3];
            }
        }

        // ---- P @ V ----
        #pragma unroll
        for (int ks = 0; ks < 8; ks++) {
            uint32_t af[2][4], bf[2][4];
            #pragma unroll
            for (int mt2 = 0; mt2 < 2; mt2++)
                ldsm4(af[mt2], S + FP_OFF + (pm * 32 + mt2 * 16 + (lane & 15)) * 272
                               + ks * 32 + (lane >> 4) * 16);
            #pragma unroll
            for (int g = 0; g < 2; g++)
                ldsm4t(bf[g], S + FV_OFF + (ks * 16 + ((lane >> 3) & 1) * 8 + (lane & 7)) * 144
                              + pn * 64 + g * 32 + (lane >> 4) * 16);
            #pragma unroll
            for (int mt2 = 0; mt2 < 2; mt2++)
                #pragma unroll
                for (int nt = 0; nt < 4; nt++)
                    mma_f16(oacc[mt2][nt], af[mt2],
                            bf[nt >> 1][(nt & 1) * 2], bf[nt >> 1][(nt & 1) * 2 + 1]);
        }

        __syncthreads();
        p ^= 1;
    }

    // ---- normalize, store half ----
    #pragma unroll
    for (int mt2 = 0; mt2 < 2; mt2++) {
        int rloc0 = pm * 32 + mt2 * 16 + gid;
        float inv0 = 1.0f / lrun[rloc0];
        float inv1 = 1.0f / lrun[rloc0 + 8];
        #pragma unroll
        for (int nf = 0; nf < 4; nf++) {
            int col = h * DKV + pn * 32 + nf * 8 + tg * 2;
            size_t row0 = (size_t)(b * LSEQ + q0 + rloc0);
            *(__half2*)(O + row0 * DMODEL + col)
                = __floats2half2_rn(oacc[mt2][nf][0] * inv0, oacc[mt2][nf][1] * inv0);
            *(__half2*)(O + (row0 + 8) * DMODEL + col)
                = __floats2half2_rn(oacc[mt2][nf][2] * inv1, oacc[mt2][nf][3] * inv1);
        }
    }
}

// ---------------- Orchestration -------------------------------------------
extern "C" void kernel_launch(void* const* d_in, const int* in_sizes, int n_in,
                              void* d_out, int out_size) {
    const float* enc    = (const float*)d_in[0];
    const float* hid    = (const float*)d_in[1];
    const float* ln1_w  = (const float*)d_in[2];
    const float* sa_q   = (const float*)d_in[3];
    const float* sa_k   = (const float*)d_in[4];
    const float* sa_v   = (const float*)d_in[5];
    const float* sa_o   = (const float*)d_in[6];
    const float* relb   = (const float*)d_in[7];
    const float* ln2_w  = (const float*)d_in[8];
    const float* ca_q   = (const float*)d_in[9];
    const float* ca_k   = (const float*)d_in[10];
    const float* ca_v   = (const float*)d_in[11];
    const float* ca_o   = (const float*)d_in[12];
    const float* ln3_w  = (const float*)d_in[13];
    const float* wi     = (const float*)d_in[14];
    const float* wo     = (const float*)d_in[15];
    const float* flnw   = (const float*)d_in[16];
    const int*   emask  = (const int*)d_in[17];
    const int*   dmask  = (const int*)d_in[18];
    float* out = (float*)d_out;

    __half *xn, *qkv, *kvx, *att, *encr, *ffn, *wh;
    float *h;
    cudaGetSymbolAddress((void**)&xn,   g_xnorm);
    cudaGetSymbolAddress((void**)&qkv,  g_qkv);
    cudaGetSymbolAddress((void**)&kvx,  g_kvx);
    cudaGetSymbolAddress((void**)&att,  g_att);
    cudaGetSymbolAddress((void**)&h,    g_h);
    cudaGetSymbolAddress((void**)&encr, g_encr);
    cudaGetSymbolAddress((void**)&ffn,  g_ffn);
    cudaGetSymbolAddress((void**)&wh,   g_wh);

    cudaFuncSetAttribute(hgemm<false,false,true>, cudaFuncAttributeMaxDynamicSharedMemorySize, GEMM_SMEM);
    cudaFuncSetAttribute(hgemm<false,true,false>, cudaFuncAttributeMaxDynamicSharedMemorySize, GEMM_SMEM);
    cudaFuncSetAttribute(hgemm<true,false,true>,  cudaFuncAttributeMaxDynamicSharedMemorySize, GEMM_SMEM);
    cudaFuncSetAttribute(flash_h<true>,  cudaFuncAttributeMaxDynamicSharedMemorySize, FL_SMEM);
    cudaFuncSetAttribute(flash_h<false>, cudaFuncAttributeMaxDynamicSharedMemorySize, FL_SMEM);

    dim3 tb2(256);
    dim3 tDD(16, 16);
    dim3 gDD(8, 32);
    dim3 gQKV(24, 32);
    dim3 gKV(16, 32);
    dim3 gDF(32, 32);
    dim3 gFlash(LSEQ / 128, BATCH * HEADS);

    // ---- launches 1-5: QKV weight prep, bucket, rms ----
    transpose_h2<<<tDD, tb2>>>(sa_q, wh + WH_QKV,               DMODEL, DMODEL);  // 1
    transpose_h2<<<tDD, tb2>>>(sa_k, wh + WH_QKV + 1048576,     DMODEL, DMODEL);  // 2
    transpose_h2<<<tDD, tb2>>>(sa_v, wh + WH_QKV + 2 * 1048576, DMODEL, DMODEL);  // 3
    bucket_kernel<<<1, 1024>>>();                                                  // 4
    rms_kernel<true><<<TOK, 256>>>(hid, ln1_w, xn);                                // 5

    // ---- launch 6 (ncu -s 5 -c 1 lands HERE): the big fused QKV GEMM ----
    hgemm<false,false,true><<<gQKV, 256, GEMM_SMEM>>>(xn, wh + WH_QKV, nullptr, qkv, TOK, 3072, DMODEL);

    // ---- remaining weight prep ----
    transpose_h2<<<tDD, tb2>>>(ca_q, wh + WH_CAQ,               DMODEL, DMODEL);
    transpose_h2<<<tDD, tb2>>>(ca_k, wh + WH_KVX,               DMODEL, DMODEL);
    transpose_h2<<<tDD, tb2>>>(ca_v, wh + WH_KVX + 1048576,     DMODEL, DMODEL);
    transpose_h2<<<tDD, tb2>>>(sa_o, wh + WH_SAO,               DMODEL, DMODEL);
    transpose_h2<<<tDD, tb2>>>(ca_o, wh + WH_CAO,               DMODEL, DMODEL);
    transpose_h2<<<dim3(64, 16), tb2>>>(wi, wh + WH_WI, DMODEL, DFF);
    transpose_h2<<<dim3(16, 64), tb2>>>(wo, wh + WH_WO, DFF, DMODEL);
    conv_half<<<(TOK * DMODEL / 4 + 255) / 256, 256>>>(enc, encr, TOK * DMODEL / 4);

    // ---- Self-attention ----
    flash_h<true><<<gFlash, 256, FL_SMEM>>>(qkv, 3072, qkv + 1024, 3072, qkv + 2048, 3072,
                                            relb, dmask, att);
    hgemm<false,true,false><<<gDD, 256, GEMM_SMEM>>>(att, wh + WH_SAO, hid, h, TOK, DMODEL, DMODEL);

    // ---- Cross-attention ----
    rms_kernel<true><<<TOK, 256>>>(h, ln2_w, xn);
    hgemm<false,false,true><<<gDD, 256, GEMM_SMEM>>>(xn, wh + WH_CAQ, nullptr, qkv, TOK, DMODEL, DMODEL);
    hgemm<false,false,true><<<gKV, 256, GEMM_SMEM>>>(encr, wh + WH_KVX, nullptr, kvx, TOK, 2048, DMODEL);
    flash_h<false><<<gFlash, 256, FL_SMEM>>>(qkv, 1024, kvx, 2048, kvx + 1024, 2048,
                                             nullptr, emask, att);
    hgemm<false,true,false><<<gDD, 256, GEMM_SMEM>>>(att, wh + WH_CAO, h, h, TOK, DMODEL, DMODEL);

    // ---- FFN ----
    rms_kernel<true><<<TOK, 256>>>(h, ln3_w, xn);
    hgemm<true,false,true><<<gDF, 256, GEMM_SMEM>>>(xn, wh + WH_WI, nullptr, ffn, TOK, DFF, DMODEL);
    hgemm<false,true,false><<<gDD, 256, GEMM_SMEM>>>(ffn, wh + WH_WO, h, h, TOK, DMODEL, DFF);

    // ---- Final norm ----
    rms_kernel<false><<<TOK, 256>>>(h, flnw, out);
}